// round 6
// baseline (speedup 1.0000x reference)
#include <cuda_runtime.h>
#include <cuda_bf16.h>
#include <cstdint>

#define N_NODES 50000
#define D_FEAT  64
#define H_FEAT  128

// Scratch: neighbor-sum accumulator + duplicated-weight buffers
__device__ float g_acc[(size_t)N_NODES * D_FEAT];
__device__ unsigned long long g_W1d[D_FEAT * H_FEAT];   // {w,w} pairs, 64 KB
__device__ unsigned long long g_W2d[H_FEAT * D_FEAT];   // {w,w} pairs, 64 KB

// ---- packed f32x2 helpers -------------------------------------------------
#define FMA2(d, a, b, c) \
    asm("fma.rn.f32x2 %0, %1, %2, %3;" : "=l"(d) : "l"(a), "l"(b), "l"(c))
#define PACK2(d, lo, hi) \
    asm("mov.b64 %0, {%1, %2};" : "=l"(d) : "f"(lo), "f"(hi))
#define UNPACK2(lo, hi, s) \
    asm("mov.b64 {%0, %1}, %2;" : "=f"(lo), "=f"(hi) : "l"(s))

// ---------------------------------------------------------------------------
// Kernel 1 (prep): zero g_acc (blocks [0, zb)) + duplicate weights (rest).
// ---------------------------------------------------------------------------
__global__ void prep_kernel(const float* __restrict__ W1,
                            const float* __restrict__ W2,
                            int zero4, int zb) {
    int b = blockIdx.x;
    if (b < zb) {
        int i = b * 256 + threadIdx.x;
        if (i < zero4)
            reinterpret_cast<float4*>(g_acc)[i] = make_float4(0.f, 0.f, 0.f, 0.f);
    } else {
        int i = (b - zb) * 256 + threadIdx.x;
        if (i < D_FEAT * H_FEAT) {
            float w = W1[i];
            unsigned long long p; PACK2(p, w, w);
            g_W1d[i] = p;
            float w2 = W2[i];
            unsigned long long p2; PACK2(p2, w2, w2);
            g_W2d[i] = p2;
        }
    }
}

// ---------------------------------------------------------------------------
// Kernel 2: edge scatter. 8 lanes per edge; lane handles 8 floats (2 float4).
//   acc[src] += x[dst];  acc[dst] += x[src]   (red.global.add.v4.f32)
// ---------------------------------------------------------------------------
__global__ void scatter_kernel(const float* __restrict__ x,
                               const int* __restrict__ ei,
                               int E, int N) {
    int t = blockIdx.x * blockDim.x + threadIdx.x;
    int e = t >> 3;
    if (e >= E) return;
    int c = (t & 7) << 3;   // float offset of this lane's 8-float chunk

    int s = ei[e];
    int d = ei[(size_t)E + e];
    if ((unsigned)s >= (unsigned)N || (unsigned)d >= (unsigned)N) return;

    const float4* xs = reinterpret_cast<const float4*>(x + (size_t)s * D_FEAT + c);
    const float4* xd = reinterpret_cast<const float4*>(x + (size_t)d * D_FEAT + c);
    float4 vs0 = xs[0], vs1 = xs[1];
    float4 vd0 = xd[0], vd1 = xd[1];

    float* as = g_acc + (size_t)s * D_FEAT + c;
    float* ad = g_acc + (size_t)d * D_FEAT + c;

    asm volatile("red.global.add.v4.f32 [%0], {%1, %2, %3, %4};"
                 :: "l"(as), "f"(vd0.x), "f"(vd0.y), "f"(vd0.z), "f"(vd0.w) : "memory");
    asm volatile("red.global.add.v4.f32 [%0], {%1, %2, %3, %4};"
                 :: "l"(as + 4), "f"(vd1.x), "f"(vd1.y), "f"(vd1.z), "f"(vd1.w) : "memory");
    asm volatile("red.global.add.v4.f32 [%0], {%1, %2, %3, %4};"
                 :: "l"(ad), "f"(vs0.x), "f"(vs0.y), "f"(vs0.z), "f"(vs0.w) : "memory");
    asm volatile("red.global.add.v4.f32 [%0], {%1, %2, %3, %4};"
                 :: "l"(ad + 4), "f"(vs1.x), "f"(vs1.y), "f"(vs1.z), "f"(vs1.w) : "memory");
}

// ---------------------------------------------------------------------------
// Kernel 3: fused GIN MLP, packed f32x2 over NODE PAIRS with pre-dup weights.
//   v = g_acc[node] + (1+eps)*x[node];  y = relu(v @ W1 + b1) @ W2 + b2
// ---------------------------------------------------------------------------
#define NT 32
#define VP 34   // even -> all 64-bit smem accesses are 8B-aligned

__global__ __launch_bounds__(256, 4)
void mlp_kernel(const float* __restrict__ x,
                const float* __restrict__ eps,
                const float* __restrict__ b1,
                const float* __restrict__ b2,
                float* __restrict__ out, int N) {
    __shared__ float Vt[D_FEAT * VP];   // Vt[k][n]
    __shared__ float Ht[H_FEAT * VP];   // Ht[j][n]

    const int t  = threadIdx.x;
    const int n0 = blockIdx.x * NT;
    const float se = 1.0f + __ldg(eps);

    // ---- stage V transposed: v = acc + se*x ----
    for (int idx = t; idx < NT * D_FEAT; idx += 256) {
        int n = idx >> 6;
        int k = idx & 63;
        int node = n0 + n;
        float v = 0.0f;
        if (node < N) {
            size_t off = (size_t)node * D_FEAT + k;
            v = fmaf(se, x[off], g_acc[off]);
        }
        Vt[k * VP + n] = v;
    }
    __syncthreads();

    // ---- GEMM1: H[NT][128] = relu(V @ W1 + b1) ----
    {
        const int tx = t & 31;       // 32 * 4 = 128 j-columns
        const int ty = t >> 5;       // 8 groups * 4 nodes = 32 nodes
        const int j4 = tx * 4;
        const int nb = ty * 4;

        unsigned long long a2[2][4];   // [node-pair][col]
        {
            float4 bb = *reinterpret_cast<const float4*>(b1 + j4);
            unsigned long long p0, p1, p2, p3;
            PACK2(p0, bb.x, bb.x); PACK2(p1, bb.y, bb.y);
            PACK2(p2, bb.z, bb.z); PACK2(p3, bb.w, bb.w);
            a2[0][0] = p0; a2[0][1] = p1; a2[0][2] = p2; a2[0][3] = p3;
            a2[1][0] = p0; a2[1][1] = p1; a2[1][2] = p2; a2[1][3] = p3;
        }

        #pragma unroll 8
        for (int k = 0; k < D_FEAT; k++) {
            const unsigned long long* wr = g_W1d + k * H_FEAT + j4;
            ulonglong2 wa = *reinterpret_cast<const ulonglong2*>(wr);
            ulonglong2 wb = *reinterpret_cast<const ulonglong2*>(wr + 2);
            unsigned long long v01 =
                *reinterpret_cast<const unsigned long long*>(&Vt[k * VP + nb]);
            unsigned long long v23 =
                *reinterpret_cast<const unsigned long long*>(&Vt[k * VP + nb + 2]);
            FMA2(a2[0][0], v01, wa.x, a2[0][0]);
            FMA2(a2[0][1], v01, wa.y, a2[0][1]);
            FMA2(a2[0][2], v01, wb.x, a2[0][2]);
            FMA2(a2[0][3], v01, wb.y, a2[0][3]);
            FMA2(a2[1][0], v23, wa.x, a2[1][0]);
            FMA2(a2[1][1], v23, wa.y, a2[1][1]);
            FMA2(a2[1][2], v23, wb.x, a2[1][2]);
            FMA2(a2[1][3], v23, wb.y, a2[1][3]);
        }

        #pragma unroll
        for (int jj = 0; jj < 4; jj++) {
            #pragma unroll
            for (int i = 0; i < 2; i++) {
                float lo, hi;
                UNPACK2(lo, hi, a2[i][jj]);
                lo = fmaxf(lo, 0.0f);
                hi = fmaxf(hi, 0.0f);
                unsigned long long p; PACK2(p, lo, hi);
                *reinterpret_cast<unsigned long long*>(
                    &Ht[(j4 + jj) * VP + nb + 2 * i]) = p;
            }
        }
    }
    __syncthreads();

    // ---- GEMM2: Y[NT][64] = H @ W2 + b2 ----
    {
        const int tx = t & 15;       // 16 * 4 = 64 d-columns
        const int ty = t >> 4;       // 16 pairs * 2 nodes = 32 nodes
        const int d4 = tx * 4;
        const int nb = ty * 2;

        unsigned long long a2[4];    // [col], packed over node pair
        {
            float4 bb = *reinterpret_cast<const float4*>(b2 + d4);
            PACK2(a2[0], bb.x, bb.x);
            PACK2(a2[1], bb.y, bb.y);
            PACK2(a2[2], bb.z, bb.z);
            PACK2(a2[3], bb.w, bb.w);
        }

        #pragma unroll 8
        for (int j = 0; j < H_FEAT; j++) {
            const unsigned long long* wr = g_W2d + j * D_FEAT + d4;
            ulonglong2 wa = *reinterpret_cast<const ulonglong2*>(wr);
            ulonglong2 wb = *reinterpret_cast<const ulonglong2*>(wr + 2);
            unsigned long long h01 =
                *reinterpret_cast<const unsigned long long*>(&Ht[j * VP + nb]);
            FMA2(a2[0], h01, wa.x, a2[0]);
            FMA2(a2[1], h01, wa.y, a2[1]);
            FMA2(a2[2], h01, wb.x, a2[2]);
            FMA2(a2[3], h01, wb.y, a2[3]);
        }

        float l0, h0, l1, h1, l2, h2, l3, h3;
        UNPACK2(l0, h0, a2[0]);
        UNPACK2(l1, h1, a2[1]);
        UNPACK2(l2, h2, a2[2]);
        UNPACK2(l3, h3, a2[3]);

        int node0 = n0 + nb;
        if (node0 < N)
            *reinterpret_cast<float4*>(out + (size_t)node0 * D_FEAT + d4) =
                make_float4(l0, l1, l2, l3);
        if (node0 + 1 < N)
            *reinterpret_cast<float4*>(out + (size_t)(node0 + 1) * D_FEAT + d4) =
                make_float4(h0, h1, h2, h3);
    }
}

// ---------------------------------------------------------------------------
// Launch
// ---------------------------------------------------------------------------
extern "C" void kernel_launch(void* const* d_in, const int* in_sizes, int n_in,
                              void* d_out, int out_size) {
    const float* x   = (const float*)d_in[0];
    const float* W1  = (const float*)d_in[1];
    const float* b1  = (const float*)d_in[2];
    const float* W2  = (const float*)d_in[3];
    const float* b2  = (const float*)d_in[4];
    const float* eps = (const float*)d_in[5];
    const int*   ei  = (const int*)d_in[6];
    float* out = (float*)d_out;

    const int N = in_sizes[0] / D_FEAT;     // 50000
    const int E = in_sizes[6] / 2;          // 800000

    // 1) prep: zero acc + dup weights
    int zero4 = N * D_FEAT / 4;                       // 800000 float4
    int zb = (zero4 + 255) / 256;                     // 3125 blocks
    int db = (D_FEAT * H_FEAT + 255) / 256;           // 32 blocks
    prep_kernel<<<zb + db, 256>>>(W1, W2, zero4, zb);

    // 2) edge scatter (8 lanes / edge)
    long long threads = (long long)E * 8;
    int blocks = (int)((threads + 255) / 256);
    scatter_kernel<<<blocks, 256>>>(x, ei, E, N);

    // 3) fused MLP
    mlp_kernel<<<(N + NT - 1) / NT, 256>>>(x, eps, b1, b2, out, N);
}

// round 7
// speedup vs baseline: 1.1266x; 1.1266x over previous
#include <cuda_runtime.h>
#include <cuda_bf16.h>
#include <cstdint>

#define N_NODES 50000
#define D_FEAT  64
#define H_FEAT  128

// Scratch: neighbor-sum accumulator + duplicated-weight buffers
__device__ float g_acc[(size_t)N_NODES * D_FEAT];
__device__ unsigned long long g_W1d[D_FEAT * H_FEAT];   // {w,w} pairs
__device__ unsigned long long g_W2d[H_FEAT * D_FEAT];   // {w,w} pairs

// ---- packed f32x2 helpers -------------------------------------------------
#define FMA2(d, a, b, c) \
    asm("fma.rn.f32x2 %0, %1, %2, %3;" : "=l"(d) : "l"(a), "l"(b), "l"(c))
#define PACK2(d, lo, hi) \
    asm("mov.b64 %0, {%1, %2};" : "=l"(d) : "f"(lo), "f"(hi))
#define UNPACK2(lo, hi, s) \
    asm("mov.b64 {%0, %1}, %2;" : "=f"(lo), "=f"(hi) : "l"(s))

// ---------------------------------------------------------------------------
// Kernel 1 (prep): zero g_acc (blocks [0, zb)) + duplicate weights (rest).
// ---------------------------------------------------------------------------
__global__ void prep_kernel(const float* __restrict__ W1,
                            const float* __restrict__ W2,
                            int zero4, int zb) {
    int b = blockIdx.x;
    if (b < zb) {
        int i = b * 256 + threadIdx.x;
        if (i < zero4)
            reinterpret_cast<float4*>(g_acc)[i] = make_float4(0.f, 0.f, 0.f, 0.f);
    } else {
        int i = (b - zb) * 256 + threadIdx.x;
        if (i < D_FEAT * H_FEAT) {
            float w = W1[i];
            unsigned long long p; PACK2(p, w, w);
            g_W1d[i] = p;
            float w2 = W2[i];
            unsigned long long p2; PACK2(p2, w2, w2);
            g_W2d[i] = p2;
        }
    }
}

// ---------------------------------------------------------------------------
// Kernel 2: edge scatter. 16 lanes per edge; lane c handles ONE contiguous
// float4 chunk -> each red.v4 across the 16-lane group covers a contiguous
// 256B row span (full-density L2 wavefronts).
// ---------------------------------------------------------------------------
__global__ void scatter_kernel(const float* __restrict__ x,
                               const int* __restrict__ ei,
                               int E, int N) {
    int t = blockIdx.x * blockDim.x + threadIdx.x;
    int e = t >> 4;
    if (e >= E) return;
    int c = (t & 15) << 2;

    int s = ei[e];
    int d = ei[(size_t)E + e];
    if ((unsigned)s >= (unsigned)N || (unsigned)d >= (unsigned)N) return;

    const float4 vs = *reinterpret_cast<const float4*>(x + (size_t)s * D_FEAT + c);
    const float4 vd = *reinterpret_cast<const float4*>(x + (size_t)d * D_FEAT + c);

    float* as = g_acc + (size_t)s * D_FEAT + c;
    float* ad = g_acc + (size_t)d * D_FEAT + c;

    asm volatile("red.global.add.v4.f32 [%0], {%1, %2, %3, %4};"
                 :: "l"(as), "f"(vd.x), "f"(vd.y), "f"(vd.z), "f"(vd.w) : "memory");
    asm volatile("red.global.add.v4.f32 [%0], {%1, %2, %3, %4};"
                 :: "l"(ad), "f"(vs.x), "f"(vs.y), "f"(vs.z), "f"(vs.w) : "memory");
}

// ---------------------------------------------------------------------------
// Kernel 3: fused GIN MLP, packed f32x2 over NODE PAIRS with pre-dup weights.
//   v = g_acc[node] + (1+eps)*x[node];  y = relu(v @ W1 + b1) @ W2 + b2
// ---------------------------------------------------------------------------
#define NT 32
#define VP 34   // even -> all 64-bit smem accesses are 8B-aligned

__global__ __launch_bounds__(256, 4)
void mlp_kernel(const float* __restrict__ x,
                const float* __restrict__ eps,
                const float* __restrict__ b1,
                const float* __restrict__ b2,
                float* __restrict__ out, int N) {
    __shared__ float Vt[D_FEAT * VP];   // Vt[k][n]
    __shared__ float Ht[H_FEAT * VP];   // Ht[j][n]

    const int t  = threadIdx.x;
    const int n0 = blockIdx.x * NT;
    const float se = 1.0f + __ldg(eps);

    // ---- stage V transposed: v = acc + se*x ----
    for (int idx = t; idx < NT * D_FEAT; idx += 256) {
        int n = idx >> 6;
        int k = idx & 63;
        int node = n0 + n;
        float v = 0.0f;
        if (node < N) {
            size_t off = (size_t)node * D_FEAT + k;
            v = fmaf(se, x[off], g_acc[off]);
        }
        Vt[k * VP + n] = v;
    }
    __syncthreads();

    // ---- GEMM1: H[NT][128] = relu(V @ W1 + b1) ----
    {
        const int tx = t & 31;       // 32 * 4 = 128 j-columns
        const int ty = t >> 5;       // 8 groups * 4 nodes = 32 nodes
        const int j4 = tx * 4;
        const int nb = ty * 4;

        unsigned long long a2[2][4];   // [node-pair][col]
        {
            float4 bb = *reinterpret_cast<const float4*>(b1 + j4);
            unsigned long long p0, p1, p2, p3;
            PACK2(p0, bb.x, bb.x); PACK2(p1, bb.y, bb.y);
            PACK2(p2, bb.z, bb.z); PACK2(p3, bb.w, bb.w);
            a2[0][0] = p0; a2[0][1] = p1; a2[0][2] = p2; a2[0][3] = p3;
            a2[1][0] = p0; a2[1][1] = p1; a2[1][2] = p2; a2[1][3] = p3;
        }

        #pragma unroll 8
        for (int k = 0; k < D_FEAT; k++) {
            const unsigned long long* wr = g_W1d + k * H_FEAT + j4;
            ulonglong2 wa = *reinterpret_cast<const ulonglong2*>(wr);
            ulonglong2 wb = *reinterpret_cast<const ulonglong2*>(wr + 2);
            unsigned long long v01 =
                *reinterpret_cast<const unsigned long long*>(&Vt[k * VP + nb]);
            unsigned long long v23 =
                *reinterpret_cast<const unsigned long long*>(&Vt[k * VP + nb + 2]);
            FMA2(a2[0][0], v01, wa.x, a2[0][0]);
            FMA2(a2[0][1], v01, wa.y, a2[0][1]);
            FMA2(a2[0][2], v01, wb.x, a2[0][2]);
            FMA2(a2[0][3], v01, wb.y, a2[0][3]);
            FMA2(a2[1][0], v23, wa.x, a2[1][0]);
            FMA2(a2[1][1], v23, wa.y, a2[1][1]);
            FMA2(a2[1][2], v23, wb.x, a2[1][2]);
            FMA2(a2[1][3], v23, wb.y, a2[1][3]);
        }

        #pragma unroll
        for (int jj = 0; jj < 4; jj++) {
            #pragma unroll
            for (int i = 0; i < 2; i++) {
                float lo, hi;
                UNPACK2(lo, hi, a2[i][jj]);
                lo = fmaxf(lo, 0.0f);
                hi = fmaxf(hi, 0.0f);
                unsigned long long p; PACK2(p, lo, hi);
                *reinterpret_cast<unsigned long long*>(
                    &Ht[(j4 + jj) * VP + nb + 2 * i]) = p;
            }
        }
    }
    __syncthreads();

    // ---- GEMM2: Y[NT][64] = H @ W2 + b2 ----
    {
        const int tx = t & 15;       // 16 * 4 = 64 d-columns
        const int ty = t >> 4;       // 16 pairs * 2 nodes = 32 nodes
        const int d4 = tx * 4;
        const int nb = ty * 2;

        unsigned long long a2[4];    // [col], packed over node pair
        {
            float4 bb = *reinterpret_cast<const float4*>(b2 + d4);
            PACK2(a2[0], bb.x, bb.x);
            PACK2(a2[1], bb.y, bb.y);
            PACK2(a2[2], bb.z, bb.z);
            PACK2(a2[3], bb.w, bb.w);
        }

        #pragma unroll 8
        for (int j = 0; j < H_FEAT; j++) {
            const unsigned long long* wr = g_W2d + j * D_FEAT + d4;
            ulonglong2 wa = *reinterpret_cast<const ulonglong2*>(wr);
            ulonglong2 wb = *reinterpret_cast<const ulonglong2*>(wr + 2);
            unsigned long long h01 =
                *reinterpret_cast<const unsigned long long*>(&Ht[j * VP + nb]);
            FMA2(a2[0], h01, wa.x, a2[0]);
            FMA2(a2[1], h01, wa.y, a2[1]);
            FMA2(a2[2], h01, wb.x, a2[2]);
            FMA2(a2[3], h01, wb.y, a2[3]);
        }

        float l0, h0, l1, h1, l2, h2, l3, h3;
        UNPACK2(l0, h0, a2[0]);
        UNPACK2(l1, h1, a2[1]);
        UNPACK2(l2, h2, a2[2]);
        UNPACK2(l3, h3, a2[3]);

        int node0 = n0 + nb;
        if (node0 < N)
            *reinterpret_cast<float4*>(out + (size_t)node0 * D_FEAT + d4) =
                make_float4(l0, l1, l2, l3);
        if (node0 + 1 < N)
            *reinterpret_cast<float4*>(out + (size_t)(node0 + 1) * D_FEAT + d4) =
                make_float4(h0, h1, h2, h3);
    }
}

// ---------------------------------------------------------------------------
// Launch
// ---------------------------------------------------------------------------
extern "C" void kernel_launch(void* const* d_in, const int* in_sizes, int n_in,
                              void* d_out, int out_size) {
    const float* x   = (const float*)d_in[0];
    const float* W1  = (const float*)d_in[1];
    const float* b1  = (const float*)d_in[2];
    const float* W2  = (const float*)d_in[3];
    const float* b2  = (const float*)d_in[4];
    const float* eps = (const float*)d_in[5];
    const int*   ei  = (const int*)d_in[6];
    float* out = (float*)d_out;

    const int N = in_sizes[0] / D_FEAT;     // 50000
    const int E = in_sizes[6] / 2;          // 800000

    // 1) prep: zero acc + dup weights
    int zero4 = N * D_FEAT / 4;
    int zb = (zero4 + 255) / 256;
    int db = (D_FEAT * H_FEAT + 255) / 256;
    prep_kernel<<<zb + db, 256>>>(W1, W2, zero4, zb);

    // 2) edge scatter (16 lanes / edge, contiguous)
    long long threads = (long long)E * 16;
    int blocks = (int)((threads + 255) / 256);
    scatter_kernel<<<blocks, 256>>>(x, ei, E, N);

    // 3) fused MLP
    mlp_kernel<<<(N + NT - 1) / NT, 256>>>(x, eps, b1, b2, out, N);
}

// round 8
// speedup vs baseline: 1.4809x; 1.3145x over previous
#include <cuda_runtime.h>
#include <cuda_bf16.h>
#include <cstdint>

#define N_NODES 50000
#define D_FEAT  64
#define H_FEAT  128

// Neighbor-sum accumulator. Zero-initialized at module load; the MLP kernel
// re-zeroes it after reading, so every kernel_launch starts from zeros.
__device__ float g_acc[(size_t)N_NODES * D_FEAT];

// ---- packed f32x2 helpers -------------------------------------------------
#define FMA2(d, a, b, c) \
    asm("fma.rn.f32x2 %0, %1, %2, %3;" : "=l"(d) : "l"(a), "l"(b), "l"(c))
#define PACK2(d, lo, hi) \
    asm("mov.b64 %0, {%1, %2};" : "=l"(d) : "f"(lo), "f"(hi))
#define UNPACK2(lo, hi, s) \
    asm("mov.b64 {%0, %1}, %2;" : "=f"(lo), "=f"(hi) : "l"(s))

// ---------------------------------------------------------------------------
// Kernel 1: edge scatter. 16 lanes per edge; lane c handles ONE contiguous
// float4 chunk -> each red.v4 across the 16-lane group covers a contiguous
// 256B row span (full-density L2 wavefronts).
//   acc[src] += x[dst];  acc[dst] += x[src]
// ---------------------------------------------------------------------------
__global__ void scatter_kernel(const float* __restrict__ x,
                               const int* __restrict__ ei,
                               int E, int N) {
    int t = blockIdx.x * blockDim.x + threadIdx.x;
    int e = t >> 4;
    if (e >= E) return;
    int c = (t & 15) << 2;

    int s = ei[e];
    int d = ei[(size_t)E + e];
    if ((unsigned)s >= (unsigned)N || (unsigned)d >= (unsigned)N) return;

    const float4 vs = *reinterpret_cast<const float4*>(x + (size_t)s * D_FEAT + c);
    const float4 vd = *reinterpret_cast<const float4*>(x + (size_t)d * D_FEAT + c);

    float* as = g_acc + (size_t)s * D_FEAT + c;
    float* ad = g_acc + (size_t)d * D_FEAT + c;

    asm volatile("red.global.add.v4.f32 [%0], {%1, %2, %3, %4};"
                 :: "l"(as), "f"(vd.x), "f"(vd.y), "f"(vd.z), "f"(vd.w) : "memory");
    asm volatile("red.global.add.v4.f32 [%0], {%1, %2, %3, %4};"
                 :: "l"(ad), "f"(vs.x), "f"(vs.y), "f"(vs.z), "f"(vs.w) : "memory");
}

// ---------------------------------------------------------------------------
// Kernel 2: fused GIN MLP (R5-proven GEMM core, compact weights).
//   v = g_acc[node] + (1+eps)*x[node];  g_acc[node] = 0  (self-clean)
//   y = relu(v @ W1 + b1) @ W2 + b2
// ---------------------------------------------------------------------------
#define NT 32
#define VP 33

__global__ __launch_bounds__(256, 4)
void mlp_kernel(const float* __restrict__ x,
                const float* __restrict__ eps,
                const float* __restrict__ W1, const float* __restrict__ b1,
                const float* __restrict__ W2, const float* __restrict__ b2,
                float* __restrict__ out, int N) {
    __shared__ float Vt[D_FEAT * VP];   // Vt[k][n]
    __shared__ float Ht[H_FEAT * VP];   // Ht[j][n]

    const int t  = threadIdx.x;
    const int n0 = blockIdx.x * NT;
    const float se = 1.0f + __ldg(eps);

    // ---- stage V transposed: v = acc + se*x; acc = 0 ----
    for (int idx = t; idx < NT * D_FEAT; idx += 256) {
        int n = idx >> 6;
        int k = idx & 63;
        int node = n0 + n;
        float v = 0.0f;
        if (node < N) {
            size_t off = (size_t)node * D_FEAT + k;
            v = fmaf(se, x[off], g_acc[off]);
            g_acc[off] = 0.0f;          // self-clean for next launch
        }
        Vt[k * VP + n] = v;
    }
    __syncthreads();

    // ---- GEMM1: H[NT][128] = relu(V @ W1 + b1) ----
    {
        const int tx = t & 31;       // 32 * 4 = 128 j-columns
        const int ty = t >> 5;       // 8 * 4 = 32 nodes
        const int j4 = tx * 4;
        const int nb = ty * 4;

        unsigned long long a2[4][2];   // [node][pair]
        {
            ulonglong2 bb = *reinterpret_cast<const ulonglong2*>(b1 + j4);
            #pragma unroll
            for (int i = 0; i < 4; i++) { a2[i][0] = bb.x; a2[i][1] = bb.y; }
        }

        #pragma unroll 8
        for (int k = 0; k < D_FEAT; k++) {
            ulonglong2 w = *reinterpret_cast<const ulonglong2*>(W1 + k * H_FEAT + j4);
            float s0 = Vt[k * VP + nb + 0];
            float s1 = Vt[k * VP + nb + 1];
            float s2 = Vt[k * VP + nb + 2];
            float s3 = Vt[k * VP + nb + 3];
            unsigned long long v0, v1, v2, v3;
            PACK2(v0, s0, s0);
            PACK2(v1, s1, s1);
            PACK2(v2, s2, s2);
            PACK2(v3, s3, s3);
            FMA2(a2[0][0], v0, w.x, a2[0][0]); FMA2(a2[0][1], v0, w.y, a2[0][1]);
            FMA2(a2[1][0], v1, w.x, a2[1][0]); FMA2(a2[1][1], v1, w.y, a2[1][1]);
            FMA2(a2[2][0], v2, w.x, a2[2][0]); FMA2(a2[2][1], v2, w.y, a2[2][1]);
            FMA2(a2[3][0], v3, w.x, a2[3][0]); FMA2(a2[3][1], v3, w.y, a2[3][1]);
        }

        #pragma unroll
        for (int i = 0; i < 4; i++) {
            float l0, h0, l1, h1;
            UNPACK2(l0, h0, a2[i][0]);
            UNPACK2(l1, h1, a2[i][1]);
            Ht[(j4 + 0) * VP + nb + i] = fmaxf(l0, 0.0f);
            Ht[(j4 + 1) * VP + nb + i] = fmaxf(h0, 0.0f);
            Ht[(j4 + 2) * VP + nb + i] = fmaxf(l1, 0.0f);
            Ht[(j4 + 3) * VP + nb + i] = fmaxf(h1, 0.0f);
        }
    }
    __syncthreads();

    // ---- GEMM2: Y[NT][64] = H @ W2 + b2 ----
    {
        const int tx = t & 15;       // 16 * 4 = 64 d-columns
        const int ty = t >> 4;       // 16 * 2 = 32 nodes
        const int d4 = tx * 4;
        const int nb = ty * 2;

        unsigned long long a2[2][2];
        {
            ulonglong2 bb = *reinterpret_cast<const ulonglong2*>(b2 + d4);
            a2[0][0] = bb.x; a2[0][1] = bb.y;
            a2[1][0] = bb.x; a2[1][1] = bb.y;
        }

        #pragma unroll 8
        for (int j = 0; j < H_FEAT; j++) {
            ulonglong2 w = *reinterpret_cast<const ulonglong2*>(W2 + j * D_FEAT + d4);
            float s0 = Ht[j * VP + nb + 0];
            float s1 = Ht[j * VP + nb + 1];
            unsigned long long v0, v1;
            PACK2(v0, s0, s0);
            PACK2(v1, s1, s1);
            FMA2(a2[0][0], v0, w.x, a2[0][0]); FMA2(a2[0][1], v0, w.y, a2[0][1]);
            FMA2(a2[1][0], v1, w.x, a2[1][0]); FMA2(a2[1][1], v1, w.y, a2[1][1]);
        }

        #pragma unroll
        for (int i = 0; i < 2; i++) {
            int node = n0 + nb + i;
            if (node < N) {
                ulonglong2 y;
                y.x = a2[i][0];
                y.y = a2[i][1];
                *reinterpret_cast<ulonglong2*>(out + (size_t)node * D_FEAT + d4) = y;
            }
        }
    }
}

// ---------------------------------------------------------------------------
// Launch
// ---------------------------------------------------------------------------
extern "C" void kernel_launch(void* const* d_in, const int* in_sizes, int n_in,
                              void* d_out, int out_size) {
    const float* x   = (const float*)d_in[0];
    const float* W1  = (const float*)d_in[1];
    const float* b1  = (const float*)d_in[2];
    const float* W2  = (const float*)d_in[3];
    const float* b2  = (const float*)d_in[4];
    const float* eps = (const float*)d_in[5];
    const int*   ei  = (const int*)d_in[6];
    float* out = (float*)d_out;

    const int N = in_sizes[0] / D_FEAT;     // 50000
    const int E = in_sizes[6] / 2;          // 800000

    // 1) edge scatter (g_acc is zero on entry: zero-init at load,
    //    re-zeroed by mlp_kernel at the end of every launch)
    long long threads = (long long)E * 16;
    int blocks = (int)((threads + 255) / 256);
    scatter_kernel<<<blocks, 256>>>(x, ei, E, N);

    // 2) fused MLP (+ acc self-clean)
    mlp_kernel<<<(N + NT - 1) / NT, 256>>>(x, eps, W1, b1, W2, b2, out, N);
}

// round 9
// speedup vs baseline: 2.0576x; 1.3894x over previous
#include <cuda_runtime.h>
#include <cuda_bf16.h>
#include <cstdint>

#define N_NODES 50000
#define D_FEAT  64
#define H_FEAT  128

// Accumulator: overwritten by init each launch, so no cross-replay state.
__device__ float g_acc[(size_t)N_NODES * D_FEAT];

// ---- packed f32x2 helpers -------------------------------------------------
#define FMA2(d, a, b, c) \
    asm("fma.rn.f32x2 %0, %1, %2, %3;" : "=l"(d) : "l"(a), "l"(b), "l"(c))
#define PACK2(d, lo, hi) \
    asm("mov.b64 %0, {%1, %2};" : "=l"(d) : "f"(lo), "f"(hi))
#define UNPACK2(lo, hi, s) \
    asm("mov.b64 {%0, %1}, %2;" : "=f"(lo), "=f"(hi) : "l"(s))

// ---------------------------------------------------------------------------
// Kernel 1: acc[i] = (1+eps) * x[i]   (overwrite; proven 7us)
// ---------------------------------------------------------------------------
__global__ void init_acc_kernel(const float* __restrict__ x,
                                const float* __restrict__ eps,
                                int total4) {
    int i = blockIdx.x * blockDim.x + threadIdx.x;
    if (i >= total4) return;
    float s = 1.0f + eps[0];
    float4 v = reinterpret_cast<const float4*>(x)[i];
    v.x *= s; v.y *= s; v.z *= s; v.w *= s;
    reinterpret_cast<float4*>(g_acc)[i] = v;
}

// ---------------------------------------------------------------------------
// Kernel 2: edge scatter, 16 lanes/edge, contiguous float4 chunks (R5-proven).
// ---------------------------------------------------------------------------
__global__ void scatter_kernel(const float* __restrict__ x,
                               const int* __restrict__ ei,
                               int E, int N) {
    int t = blockIdx.x * blockDim.x + threadIdx.x;
    int e = t >> 4;
    if (e >= E) return;
    int c = (t & 15) << 2;

    int s = ei[e];
    int d = ei[(size_t)E + e];
    if ((unsigned)s >= (unsigned)N || (unsigned)d >= (unsigned)N) return;

    const float4 vs = *reinterpret_cast<const float4*>(x + (size_t)s * D_FEAT + c);
    const float4 vd = *reinterpret_cast<const float4*>(x + (size_t)d * D_FEAT + c);

    float* as = g_acc + (size_t)s * D_FEAT + c;
    float* ad = g_acc + (size_t)d * D_FEAT + c;

    asm volatile("red.global.add.v4.f32 [%0], {%1, %2, %3, %4};"
                 :: "l"(as), "f"(vd.x), "f"(vd.y), "f"(vd.z), "f"(vd.w) : "memory");
    asm volatile("red.global.add.v4.f32 [%0], {%1, %2, %3, %4};"
                 :: "l"(ad), "f"(vs.x), "f"(vs.y), "f"(vs.z), "f"(vs.w) : "memory");
}

// ---------------------------------------------------------------------------
// Kernel 3: fused GIN MLP, 64-node tiles, node-pair packed f32x2,
// compact weights (LDG.128 full-density), broadcast LDS.64 operands.
//   y = relu(acc @ W1 + b1) @ W2 + b2
// ---------------------------------------------------------------------------
#define NT 64
#define VP 66   // even pitch -> all 64-bit smem accesses 8B-aligned

__global__ __launch_bounds__(256, 4)
void mlp_kernel(const float* __restrict__ W1, const float* __restrict__ b1,
                const float* __restrict__ W2, const float* __restrict__ b2,
                float* __restrict__ out, int N) {
    extern __shared__ float smem[];
    float* Vt = smem;                    // Vt[k][n]  64 x VP
    float* Ht = smem + D_FEAT * VP;      // Ht[j][n]  128 x VP

    const int t  = threadIdx.x;
    const int n0 = blockIdx.x * NT;

    // ---- stage V transposed from g_acc ----
    for (int idx = t; idx < NT * D_FEAT; idx += 256) {
        int n = idx >> 6;        // node in tile (0..63)
        int k = idx & 63;        // feature
        int node = n0 + n;
        Vt[k * VP + n] = (node < N) ? g_acc[(size_t)node * D_FEAT + k] : 0.0f;
    }
    __syncthreads();

    // ---- GEMM1: H[64][128] = relu(V @ W1 + b1) ----
    {
        const int tx = t & 31;       // 32 * 4 = 128 j-columns
        const int ty = t >> 5;       // 8 groups * 8 nodes = 64 nodes
        const int j4 = tx * 4;
        const int nb = ty * 8;

        unsigned long long a2[4][4];   // [node-pair p][col c]
        {
            float4 bb = *reinterpret_cast<const float4*>(b1 + j4);
            unsigned long long d0, d1, d2, d3;
            PACK2(d0, bb.x, bb.x); PACK2(d1, bb.y, bb.y);
            PACK2(d2, bb.z, bb.z); PACK2(d3, bb.w, bb.w);
            #pragma unroll
            for (int p = 0; p < 4; p++) {
                a2[p][0] = d0; a2[p][1] = d1; a2[p][2] = d2; a2[p][3] = d3;
            }
        }

        #pragma unroll 4
        for (int k = 0; k < D_FEAT; k++) {
            float4 w = *reinterpret_cast<const float4*>(W1 + k * H_FEAT + j4);
            unsigned long long w0, w1, w2, w3;
            PACK2(w0, w.x, w.x); PACK2(w1, w.y, w.y);
            PACK2(w2, w.z, w.z); PACK2(w3, w.w, w.w);
            const float* vrow = &Vt[k * VP + nb];
            unsigned long long v0 = *reinterpret_cast<const unsigned long long*>(vrow);
            unsigned long long v1 = *reinterpret_cast<const unsigned long long*>(vrow + 2);
            unsigned long long v2 = *reinterpret_cast<const unsigned long long*>(vrow + 4);
            unsigned long long v3 = *reinterpret_cast<const unsigned long long*>(vrow + 6);
            FMA2(a2[0][0], v0, w0, a2[0][0]); FMA2(a2[0][1], v0, w1, a2[0][1]);
            FMA2(a2[0][2], v0, w2, a2[0][2]); FMA2(a2[0][3], v0, w3, a2[0][3]);
            FMA2(a2[1][0], v1, w0, a2[1][0]); FMA2(a2[1][1], v1, w1, a2[1][1]);
            FMA2(a2[1][2], v1, w2, a2[1][2]); FMA2(a2[1][3], v1, w3, a2[1][3]);
            FMA2(a2[2][0], v2, w0, a2[2][0]); FMA2(a2[2][1], v2, w1, a2[2][1]);
            FMA2(a2[2][2], v2, w2, a2[2][2]); FMA2(a2[2][3], v2, w3, a2[2][3]);
            FMA2(a2[3][0], v3, w0, a2[3][0]); FMA2(a2[3][1], v3, w1, a2[3][1]);
            FMA2(a2[3][2], v3, w2, a2[3][2]); FMA2(a2[3][3], v3, w3, a2[3][3]);
        }

        #pragma unroll
        for (int c = 0; c < 4; c++) {
            #pragma unroll
            for (int p = 0; p < 4; p++) {
                float lo, hi;
                UNPACK2(lo, hi, a2[p][c]);
                lo = fmaxf(lo, 0.0f);
                hi = fmaxf(hi, 0.0f);
                unsigned long long pk; PACK2(pk, lo, hi);
                *reinterpret_cast<unsigned long long*>(
                    &Ht[(j4 + c) * VP + nb + 2 * p]) = pk;
            }
        }
    }
    __syncthreads();

    // ---- GEMM2: Y[64][64] = H @ W2 + b2 ----
    {
        const int tx = t & 15;       // 16 * 4 = 64 d-columns
        const int ty = t >> 4;       // 16 groups * 4 nodes = 64 nodes
        const int d4 = tx * 4;
        const int nb = ty * 4;

        unsigned long long a2[2][4];   // [node-pair q][col c]
        {
            float4 bb = *reinterpret_cast<const float4*>(b2 + d4);
            unsigned long long d0, d1, d2, d3;
            PACK2(d0, bb.x, bb.x); PACK2(d1, bb.y, bb.y);
            PACK2(d2, bb.z, bb.z); PACK2(d3, bb.w, bb.w);
            a2[0][0] = d0; a2[0][1] = d1; a2[0][2] = d2; a2[0][3] = d3;
            a2[1][0] = d0; a2[1][1] = d1; a2[1][2] = d2; a2[1][3] = d3;
        }

        #pragma unroll 4
        for (int j = 0; j < H_FEAT; j++) {
            float4 w = *reinterpret_cast<const float4*>(W2 + j * D_FEAT + d4);
            unsigned long long w0, w1, w2, w3;
            PACK2(w0, w.x, w.x); PACK2(w1, w.y, w.y);
            PACK2(w2, w.z, w.z); PACK2(w3, w.w, w.w);
            const float* hrow = &Ht[j * VP + nb];
            unsigned long long h0 = *reinterpret_cast<const unsigned long long*>(hrow);
            unsigned long long h1 = *reinterpret_cast<const unsigned long long*>(hrow + 2);
            FMA2(a2[0][0], h0, w0, a2[0][0]); FMA2(a2[0][1], h0, w1, a2[0][1]);
            FMA2(a2[0][2], h0, w2, a2[0][2]); FMA2(a2[0][3], h0, w3, a2[0][3]);
            FMA2(a2[1][0], h1, w0, a2[1][0]); FMA2(a2[1][1], h1, w1, a2[1][1]);
            FMA2(a2[1][2], h1, w2, a2[1][2]); FMA2(a2[1][3], h1, w3, a2[1][3]);
        }

        #pragma unroll
        for (int q = 0; q < 2; q++) {
            float l0, h0, l1, h1, l2, h2, l3, h3;
            UNPACK2(l0, h0, a2[q][0]);
            UNPACK2(l1, h1, a2[q][1]);
            UNPACK2(l2, h2, a2[q][2]);
            UNPACK2(l3, h3, a2[q][3]);
            int node0 = n0 + nb + 2 * q;
            if (node0 < N)
                *reinterpret_cast<float4*>(out + (size_t)node0 * D_FEAT + d4) =
                    make_float4(l0, l1, l2, l3);
            if (node0 + 1 < N)
                *reinterpret_cast<float4*>(out + (size_t)(node0 + 1) * D_FEAT + d4) =
                    make_float4(h0, h1, h2, h3);
        }
    }
}

// ---------------------------------------------------------------------------
// Launch
// ---------------------------------------------------------------------------
extern "C" void kernel_launch(void* const* d_in, const int* in_sizes, int n_in,
                              void* d_out, int out_size) {
    const float* x   = (const float*)d_in[0];
    const float* W1  = (const float*)d_in[1];
    const float* b1  = (const float*)d_in[2];
    const float* W2  = (const float*)d_in[3];
    const float* b2  = (const float*)d_in[4];
    const float* eps = (const float*)d_in[5];
    const int*   ei  = (const int*)d_in[6];
    float* out = (float*)d_out;

    const int N = in_sizes[0] / D_FEAT;     // 50000
    const int E = in_sizes[6] / 2;          // 800000

    const int smem_bytes = (D_FEAT + H_FEAT) * VP * (int)sizeof(float); // 50688
    static int attr_set = 0;
    if (!attr_set) {
        cudaFuncSetAttribute(mlp_kernel,
                             cudaFuncAttributeMaxDynamicSharedMemorySize,
                             smem_bytes);
        attr_set = 1;
    }

    // 1) acc = (1+eps)*x   (overwrite each launch)
    int total4 = N * D_FEAT / 4;
    init_acc_kernel<<<(total4 + 255) / 256, 256>>>(x, eps, total4);

    // 2) edge scatter
    long long threads = (long long)E * 16;
    int blocks = (int)((threads + 255) / 256);
    scatter_kernel<<<blocks, 256>>>(x, ei, E, N);

    // 3) fused MLP (64-node tiles)
    mlp_kernel<<<(N + NT - 1) / NT, 256, smem_bytes>>>(W1, b1, W2, b2, out, N);
}